// round 6
// baseline (speedup 1.0000x reference)
#include <cuda_runtime.h>

#define HH 192
#define WW 192
#define CC 80
#define BB 8
#define RSTRIP 2
#define NSTRIP (HH / RSTRIP)   /* 96 */
#define NWARP 8
#define CPG (CC / NWARP)       /* 10 */
#define NPIX (BB * HH * WW)    /* 294912 */
#define HWA (HH * WW)
#define SPIX (RSTRIP * WW)     /* 384 pixels per strip */
#define THR 0.7f
#define LANES 24               /* active lanes per warp; 8 cols each = 192 */

// Two LDG.128 per lane; warp (24 lanes) spans 3 cache lines per LDG -> 3 wavefronts.
__device__ __forceinline__ void load_row8(const float* __restrict__ p, int y,
                                          bool active, float v[8]) {
    if (active && (unsigned)y < (unsigned)HH) {
        float4 a = __ldg(reinterpret_cast<const float4*>(p + y * WW));
        float4 b = __ldg(reinterpret_cast<const float4*>(p + y * WW + 4));
        v[0] = a.x; v[1] = a.y; v[2] = a.z; v[3] = a.w;
        v[4] = b.x; v[5] = b.y; v[6] = b.z; v[7] = b.w;
    } else {
#pragma unroll
        for (int i = 0; i < 8; i++) v[i] = 0.0f;
    }
}

// lr[i] = max(left neighbor, right neighbor) within the row (borders -> 0; heat >= 0)
__device__ __forceinline__ void row_lr8(const float v[8], float lr[8], int lane) {
    float vl = __shfl_up_sync(0xffffffffu, v[7], 1);
    float vr = __shfl_down_sync(0xffffffffu, v[0], 1);
    vl = (lane == 0) ? 0.0f : vl;
    vr = (lane >= LANES - 1) ? 0.0f : vr;   // lane 23's right comes from idle lane 24
    lr[0] = fmaxf(vl, v[1]);
#pragma unroll
    for (int i = 1; i < 7; i++) lr[i] = fmaxf(v[i - 1], v[i + 1]);
    lr[7] = fmaxf(v[6], vr);
}

// One block per (batch, 2-row strip). 8 warps x 10 channels each.
// Lane l (<24) owns columns [8l, 8l+8). Rolling horizontal-max pipeline
// with state {h(y-1), v(y), lr(y)}; h(y) recomputed as max(lr,v) at rotation.
__global__ void __launch_bounds__(256, 3)
fused_kernel(const float* __restrict__ heat, const float* __restrict__ box,
             float* __restrict__ out) {
    __shared__ float smem_s[NWARP][SPIX];

    const int strip = blockIdx.x;
    const int b     = blockIdx.y;
    const int wid   = threadIdx.x >> 5;
    const int lane  = threadIdx.x & 31;
    const bool act  = lane < LANES;
    const int x0 = lane * 8;
    const int y0 = strip * RSTRIP;

    const float* base = heat + (b * CC + wid * CPG) * HWA + (act ? x0 : 0);

    float s[RSTRIP][8];
#pragma unroll
    for (int r = 0; r < RSTRIP; r++)
#pragma unroll
        for (int i = 0; i < 8; i++) s[r][i] = 0.0f;

#pragma unroll 1
    for (int c = 0; c < CPG; c++) {
        const float* pl = base + c * HWA;

        float v_c[8], lr_c[8], h_m1[8];
        {   // halo row y0-1 -> h(y0-1)
            float vt[8], lrt[8];
            load_row8(pl, y0 - 1, act, vt);
            row_lr8(vt, lrt, lane);
#pragma unroll
            for (int i = 0; i < 8; i++) h_m1[i] = fmaxf(lrt[i], vt[i]);
        }
        load_row8(pl, y0, act, v_c);
        row_lr8(v_c, lr_c, lane);

#pragma unroll
        for (int r = 0; r < RSTRIP; r++) {
            float v_n[8], lr_n[8];
            load_row8(pl, y0 + r + 1, act, v_n);
            row_lr8(v_n, lr_n, lane);

            // kept <=> v >= max(h(y-1), h(y+1), lrmax(y))   (h(y) >= v trivially)
#pragma unroll
            for (int i = 0; i < 8; i++) {
                float hp1 = fmaxf(lr_n[i], v_n[i]);
                float Bv = fmaxf(fmaxf(h_m1[i], hp1), lr_c[i]);
                if (v_c[i] >= Bv) s[r][i] = fmaxf(s[r][i], v_c[i]);
            }
            // rotate: h(y) becomes new h(y-1); next row becomes center
#pragma unroll
            for (int i = 0; i < 8; i++) {
                h_m1[i] = fmaxf(lr_c[i], v_c[i]);
                v_c[i] = v_n[i];
                lr_c[i] = lr_n[i];
            }
        }
    }

    // Publish per-warp partials (lanes < 24 only).
    if (act) {
#pragma unroll
        for (int r = 0; r < RSTRIP; r++)
#pragma unroll
            for (int i = 0; i < 8; i += 4)
                *reinterpret_cast<float4*>(&smem_s[wid][r * WW + x0 + i]) =
                    make_float4(s[r][i], s[r][i + 1], s[r][i + 2], s[r][i + 3]);
    }

    __syncthreads();

    // Reduce over warps + decode + write. 384 pixels / 256 threads.
    // Output layout (float32, reference return order):
    //   [0, 4N) boxes [B,H,W,4] | [4N, 5N) mask | [5N, 6N) scores | [6N, 8N) center
    for (int p = threadIdx.x; p < SPIX; p += 256) {
        float sc = smem_s[0][p];
#pragma unroll
        for (int w = 1; w < NWARP; w++) sc = fmaxf(sc, smem_s[w][p]);
        bool m = sc > THR;

        int x = p % WW;
        int y = y0 + p / WW;
        int idx = (b * HH + y) * WW + x;

        const float* bp = box + (b * 4) * HWA + y * WW + x;
        float dx = __ldg(bp);
        float dy = __ldg(bp + HWA);
        float w_ = __ldg(bp + 2 * HWA);
        float h_ = __ldg(bp + 3 * HWA);

        float cx = ((float)x + dx) * 4.0f;
        float cy = ((float)y + dy) * 4.0f;
        float hw = (w_ * 4.0f) * 0.5f;   // exact (power-of-two scales)
        float hh = (h_ * 4.0f) * 0.5f;

        float x1 = fminf(fmaxf(cx - hw, 0.0f), 768.0f);
        float y1 = fminf(fmaxf(cy - hh, 0.0f), 768.0f);
        float x2 = fminf(fmaxf(cx + hw, 0.0f), 768.0f);
        float y2 = fminf(fmaxf(cy + hh, 0.0f), 768.0f);

        float4 bx = m ? make_float4(x1, y1, x2 - x1, y2 - y1)
                      : make_float4(0.f, 0.f, 0.f, 0.f);
        reinterpret_cast<float4*>(out)[idx] = bx;

        out[NPIX * 4 + idx] = m ? 1.0f : 0.0f;
        out[NPIX * 5 + idx] = m ? sc : 0.0f;

        float2 ct = m ? make_float2(cx, cy) : make_float2(0.f, 0.f);
        reinterpret_cast<float2*>(out + NPIX * 6)[idx] = ct;
    }
}

extern "C" void kernel_launch(void* const* d_in, const int* in_sizes, int n_in,
                              void* d_out, int out_size) {
    const float* heat = (const float*)d_in[0];
    const float* box  = (const float*)d_in[1];
    // Robust input identification: heat has 23,592,960 elements, box 1,179,648.
    if (n_in >= 2 && in_sizes[0] < in_sizes[1]) {
        const float* t = heat; heat = box; box = t;
    }
    float* out = (float*)d_out;

    fused_kernel<<<dim3(NSTRIP, BB), 256>>>(heat, box, out);
}

// round 8
// speedup vs baseline: 1.0667x; 1.0667x over previous
#include <cuda_runtime.h>

#define HH 192
#define WW 192
#define CC 80
#define BB 8
#define RSTRIP 2
#define NSTRIP (HH / RSTRIP)   /* 96 */
#define NWARP 8
#define CPG (CC / NWARP)       /* 10 */
#define CPAIR (CPG / 2)        /* 5: channels c and c+5 run interleaved */
#define NPIX (BB * HH * WW)    /* 294912 */
#define HWA (HH * WW)
#define SPIX (RSTRIP * WW)     /* 384 pixels per strip */
#define THR 0.7f

__device__ __forceinline__ void load_row6(const float* __restrict__ p, int y, float v[6]) {
    if ((unsigned)y < (unsigned)HH) {
        const float2* q = reinterpret_cast<const float2*>(p + y * WW);
        float2 a = __ldg(q);
        float2 b = __ldg(q + 1);
        float2 c = __ldg(q + 2);
        v[0] = a.x; v[1] = a.y; v[2] = b.x; v[3] = b.y; v[4] = c.x; v[5] = c.y;
    } else {
#pragma unroll
        for (int i = 0; i < 6; i++) v[i] = 0.0f;
    }
}

// lr[i] = max(left neighbor, right neighbor) within the row (borders -> 0; heat >= 0)
__device__ __forceinline__ void row_lr6(const float v[6], float lr[6], int lane) {
    float vl = __shfl_up_sync(0xffffffffu, v[5], 1);
    float vr = __shfl_down_sync(0xffffffffu, v[0], 1);
    vl = (lane == 0) ? 0.0f : vl;
    vr = (lane == 31) ? 0.0f : vr;
    lr[0] = fmaxf(vl, v[1]);
    lr[1] = fmaxf(v[0], v[2]);
    lr[2] = fmaxf(v[1], v[3]);
    lr[3] = fmaxf(v[2], v[4]);
    lr[4] = fmaxf(v[3], v[5]);
    lr[5] = fmaxf(v[4], vr);
}

// One block per (batch, 2-row strip). 8 warps; each warp owns 10 channels and
// processes them as 5 interleaved PAIRS (two independent load->shfl->max chains
// per iteration for 2x ILP/MLP). Lane l owns columns [6l, 6l+6).
// Rolling state per chain: {h(y-1), v(y), lr(y)}; h(y)=max(lr,v) recomputed at rotate.
__global__ void __launch_bounds__(256, 3)
fused_kernel(const float* __restrict__ heat, const float* __restrict__ box,
             float* __restrict__ out) {
    __shared__ float smem_s[NWARP][SPIX];

    const int strip = blockIdx.x;
    const int b     = blockIdx.y;
    const int wid   = threadIdx.x >> 5;
    const int lane  = threadIdx.x & 31;
    const int x0 = lane * 6;
    const int y0 = strip * RSTRIP;

    const float* base = heat + (b * CC + wid * CPG) * HWA + x0;

    float s[RSTRIP][6];
#pragma unroll
    for (int r = 0; r < RSTRIP; r++)
#pragma unroll
        for (int i = 0; i < 6; i++) s[r][i] = 0.0f;

#pragma unroll 1
    for (int c = 0; c < CPAIR; c++) {
        const float* pl0 = base + c * HWA;
        const float* pl1 = base + (c + CPAIR) * HWA;

        float v_c[2][6], lr_c[2][6], h_m1[2][6];

        {   // halo row y0-1 for both chains (loads issued together)
            float vt[2][6], lrt[2][6];
            load_row6(pl0, y0 - 1, vt[0]);
            load_row6(pl1, y0 - 1, vt[1]);
            row_lr6(vt[0], lrt[0], lane);
            row_lr6(vt[1], lrt[1], lane);
#pragma unroll
            for (int k = 0; k < 2; k++)
#pragma unroll
                for (int i = 0; i < 6; i++) h_m1[k][i] = fmaxf(lrt[k][i], vt[k][i]);
        }
        load_row6(pl0, y0, v_c[0]);
        load_row6(pl1, y0, v_c[1]);
        row_lr6(v_c[0], lr_c[0], lane);
        row_lr6(v_c[1], lr_c[1], lane);

#pragma unroll
        for (int r = 0; r < RSTRIP; r++) {
            float v_n[2][6], lr_n[2][6];
            load_row6(pl0, y0 + r + 1, v_n[0]);   // both loads first: 2x MLP
            load_row6(pl1, y0 + r + 1, v_n[1]);
            row_lr6(v_n[0], lr_n[0], lane);
            row_lr6(v_n[1], lr_n[1], lane);

            // kept <=> v >= max(h(y-1), h(y+1), lrmax(y))   (h(y) >= v trivially)
#pragma unroll
            for (int k = 0; k < 2; k++)
#pragma unroll
                for (int i = 0; i < 6; i++) {
                    float hp1 = fmaxf(lr_n[k][i], v_n[k][i]);
                    float Bv = fmaxf(fmaxf(h_m1[k][i], hp1), lr_c[k][i]);
                    if (v_c[k][i] >= Bv) s[r][i] = fmaxf(s[r][i], v_c[k][i]);
                }
            // rotate both pipelines (register renames under full unroll)
#pragma unroll
            for (int k = 0; k < 2; k++)
#pragma unroll
                for (int i = 0; i < 6; i++) {
                    h_m1[k][i] = fmaxf(lr_c[k][i], v_c[k][i]);
                    v_c[k][i] = v_n[k][i];
                    lr_c[k][i] = lr_n[k][i];
                }
        }
    }

    // Publish per-warp partials.
#pragma unroll
    for (int r = 0; r < RSTRIP; r++)
#pragma unroll
        for (int i = 0; i < 6; i++)
            smem_s[wid][r * WW + x0 + i] = s[r][i];

    __syncthreads();

    // Reduce over warps + decode + write. 384 pixels / 256 threads.
    // Output layout (float32, reference return order):
    //   [0, 4N) boxes [B,H,W,4] | [4N, 5N) mask | [5N, 6N) scores | [6N, 8N) center
    for (int p = threadIdx.x; p < SPIX; p += 256) {
        float sc = smem_s[0][p];
#pragma unroll
        for (int w = 1; w < NWARP; w++) sc = fmaxf(sc, smem_s[w][p]);
        bool m = sc > THR;

        int x = p % WW;
        int y = y0 + p / WW;
        int idx = (b * HH + y) * WW + x;

        const float* bp = box + (b * 4) * HWA + y * WW + x;
        float dx = __ldg(bp);
        float dy = __ldg(bp + HWA);
        float w_ = __ldg(bp + 2 * HWA);
        float h_ = __ldg(bp + 3 * HWA);

        float cx = ((float)x + dx) * 4.0f;
        float cy = ((float)y + dy) * 4.0f;
        float hw = (w_ * 4.0f) * 0.5f;   // exact (power-of-two scales)
        float hh = (h_ * 4.0f) * 0.5f;

        float x1 = fminf(fmaxf(cx - hw, 0.0f), 768.0f);
        float y1 = fminf(fmaxf(cy - hh, 0.0f), 768.0f);
        float x2 = fminf(fmaxf(cx + hw, 0.0f), 768.0f);
        float y2 = fminf(fmaxf(cy + hh, 0.0f), 768.0f);

        float4 bx = m ? make_float4(x1, y1, x2 - x1, y2 - y1)
                      : make_float4(0.f, 0.f, 0.f, 0.f);
        reinterpret_cast<float4*>(out)[idx] = bx;

        out[NPIX * 4 + idx] = m ? 1.0f : 0.0f;
        out[NPIX * 5 + idx] = m ? sc : 0.0f;

        float2 ct = m ? make_float2(cx, cy) : make_float2(0.f, 0.f);
        reinterpret_cast<float2*>(out + NPIX * 6)[idx] = ct;
    }
}

extern "C" void kernel_launch(void* const* d_in, const int* in_sizes, int n_in,
                              void* d_out, int out_size) {
    const float* heat = (const float*)d_in[0];
    const float* box  = (const float*)d_in[1];
    // Robust input identification: heat has 23,592,960 elements, box 1,179,648.
    if (n_in >= 2 && in_sizes[0] < in_sizes[1]) {
        const float* t = heat; heat = box; box = t;
    }
    float* out = (float*)d_out;

    fused_kernel<<<dim3(NSTRIP, BB), 256>>>(heat, box, out);
}

// round 9
// speedup vs baseline: 1.0755x; 1.0083x over previous
#include <cuda_runtime.h>

#define HH 192
#define WW 192
#define CC 80
#define BB 8
#define RSTRIP 2
#define ROWS_PC (RSTRIP + 2)   /* 4 rows loaded per channel (1 halo each side) */
#define NSTRIP (HH / RSTRIP)   /* 96 */
#define NWARP 8
#define CPG (CC / NWARP)       /* 10 channels per warp */
#define NPIX (BB * HH * WW)    /* 294912 */
#define HWA (HH * WW)
#define SPIX (RSTRIP * WW)     /* 384 pixels per strip */
#define THR 0.7f

__device__ __forceinline__ void load_row6(const float* __restrict__ p, int y, float v[6]) {
    if ((unsigned)y < (unsigned)HH) {
        const float2* q = reinterpret_cast<const float2*>(p + y * WW);
        float2 a = __ldg(q);
        float2 b = __ldg(q + 1);
        float2 c = __ldg(q + 2);
        v[0] = a.x; v[1] = a.y; v[2] = b.x; v[3] = b.y; v[4] = c.x; v[5] = c.y;
    } else {
#pragma unroll
        for (int i = 0; i < 6; i++) v[i] = 0.0f;
    }
}

// Load all 4 rows (y0-1 .. y0+2) of one channel: 12 independent LDG.64.
__device__ __forceinline__ void load_ch(const float* __restrict__ p, int y0,
                                        float v[ROWS_PC][6]) {
#pragma unroll
    for (int r = 0; r < ROWS_PC; r++) load_row6(p, y0 - 1 + r, v[r]);
}

// lr[i] = max(left neighbor, right neighbor) within the row (borders -> 0; heat >= 0)
__device__ __forceinline__ void row_lr6(const float v[6], float lr[6], int lane) {
    float vl = __shfl_up_sync(0xffffffffu, v[5], 1);
    float vr = __shfl_down_sync(0xffffffffu, v[0], 1);
    vl = (lane == 0) ? 0.0f : vl;
    vr = (lane == 31) ? 0.0f : vr;
    lr[0] = fmaxf(vl, v[1]);
    lr[1] = fmaxf(v[0], v[2]);
    lr[2] = fmaxf(v[1], v[3]);
    lr[3] = fmaxf(v[2], v[4]);
    lr[4] = fmaxf(v[3], v[5]);
    lr[5] = fmaxf(v[4], vr);
}

// Full NMS for one channel's 4-row batch; accumulates kept-max into s.
__device__ __forceinline__ void compute_ch(const float v[ROWS_PC][6],
                                           float s[RSTRIP][6], int lane) {
    float h[ROWS_PC][6];      // per-row 3-wide horizontal max
    float lrm[RSTRIP][6];     // lr kept only for the two output rows
#pragma unroll
    for (int r = 0; r < ROWS_PC; r++) {
        float lr[6];
        row_lr6(v[r], lr, lane);
#pragma unroll
        for (int i = 0; i < 6; i++) h[r][i] = fmaxf(lr[i], v[r][i]);
        if (r >= 1 && r <= RSTRIP) {
#pragma unroll
            for (int i = 0; i < 6; i++) lrm[r - 1][i] = lr[i];
        }
    }
    // kept <=> v >= max(h(above), h(below), lr(own row))   (h(own) >= v trivially)
#pragma unroll
    for (int r = 0; r < RSTRIP; r++)
#pragma unroll
        for (int i = 0; i < 6; i++) {
            float B = fmaxf(fmaxf(h[r][i], h[r + 2][i]), lrm[r][i]);
            if (v[r + 1][i] >= B) s[r][i] = fmaxf(s[r][i], v[r + 1][i]);
        }
}

// One block per (batch, 2-row strip). 8 warps x 10 channels each.
// Lane l owns columns [6l, 6l+6).
// PING-PONG PIPELINE: while computing channel c, channel c+1's 12 LDGs are in
// flight, keeping ~3KB/warp of DRAM reads outstanding continuously.
__global__ void __launch_bounds__(256, 2)
fused_kernel(const float* __restrict__ heat, const float* __restrict__ box,
             float* __restrict__ out) {
    __shared__ float smem_s[NWARP][SPIX];

    const int strip = blockIdx.x;
    const int b     = blockIdx.y;
    const int wid   = threadIdx.x >> 5;
    const int lane  = threadIdx.x & 31;
    const int x0 = lane * 6;
    const int y0 = strip * RSTRIP;

    const float* base = heat + (b * CC + wid * CPG) * HWA + x0;

    float s[RSTRIP][6];
#pragma unroll
    for (int r = 0; r < RSTRIP; r++)
#pragma unroll
        for (int i = 0; i < 6; i++) s[r][i] = 0.0f;

    float bufA[ROWS_PC][6], bufB[ROWS_PC][6];
    load_ch(base, y0, bufA);                       // prologue: channel 0

#pragma unroll
    for (int k = 0; k < CPG / 2; k++) {
        load_ch(base + (2 * k + 1) * HWA, y0, bufB);   // prefetch odd channel
        compute_ch(bufA, s, lane);                     // overlap with bufB loads
        if (k + 1 < CPG / 2)
            load_ch(base + (2 * k + 2) * HWA, y0, bufA); // prefetch next even
        compute_ch(bufB, s, lane);                     // overlap with bufA loads
    }

    // Publish per-warp partials.
#pragma unroll
    for (int r = 0; r < RSTRIP; r++)
#pragma unroll
        for (int i = 0; i < 6; i++)
            smem_s[wid][r * WW + x0 + i] = s[r][i];

    __syncthreads();

    // Reduce over warps + decode + write. 384 pixels / 256 threads.
    // Output layout (float32, reference return order):
    //   [0, 4N) boxes [B,H,W,4] | [4N, 5N) mask | [5N, 6N) scores | [6N, 8N) center
    for (int p = threadIdx.x; p < SPIX; p += 256) {
        float sc = smem_s[0][p];
#pragma unroll
        for (int w = 1; w < NWARP; w++) sc = fmaxf(sc, smem_s[w][p]);
        bool m = sc > THR;

        int x = p % WW;
        int y = y0 + p / WW;
        int idx = (b * HH + y) * WW + x;

        const float* bp = box + (b * 4) * HWA + y * WW + x;
        float dx = __ldg(bp);
        float dy = __ldg(bp + HWA);
        float w_ = __ldg(bp + 2 * HWA);
        float h_ = __ldg(bp + 3 * HWA);

        float cx = ((float)x + dx) * 4.0f;
        float cy = ((float)y + dy) * 4.0f;
        float hw = (w_ * 4.0f) * 0.5f;   // exact (power-of-two scales)
        float hh = (h_ * 4.0f) * 0.5f;

        float x1 = fminf(fmaxf(cx - hw, 0.0f), 768.0f);
        float y1 = fminf(fmaxf(cy - hh, 0.0f), 768.0f);
        float x2 = fminf(fmaxf(cx + hw, 0.0f), 768.0f);
        float y2 = fminf(fmaxf(cy + hh, 0.0f), 768.0f);

        float4 bx = m ? make_float4(x1, y1, x2 - x1, y2 - y1)
                      : make_float4(0.f, 0.f, 0.f, 0.f);
        reinterpret_cast<float4*>(out)[idx] = bx;

        out[NPIX * 4 + idx] = m ? 1.0f : 0.0f;
        out[NPIX * 5 + idx] = m ? sc : 0.0f;

        float2 ct = m ? make_float2(cx, cy) : make_float2(0.f, 0.f);
        reinterpret_cast<float2*>(out + NPIX * 6)[idx] = ct;
    }
}

extern "C" void kernel_launch(void* const* d_in, const int* in_sizes, int n_in,
                              void* d_out, int out_size) {
    const float* heat = (const float*)d_in[0];
    const float* box  = (const float*)d_in[1];
    // Robust input identification: heat has 23,592,960 elements, box 1,179,648.
    if (n_in >= 2 && in_sizes[0] < in_sizes[1]) {
        const float* t = heat; heat = box; box = t;
    }
    float* out = (float*)d_out;

    fused_kernel<<<dim3(NSTRIP, BB), 256>>>(heat, box, out);
}